// round 4
// baseline (speedup 1.0000x reference)
#include <cuda_runtime.h>
#include <cuda_bf16.h>
#include <math.h>

#define Bv 64
#define Lv 128
#define Hv 256
#define NEv 34
#define Dv 300

// ---------------- device scratch ----------------
__device__ float g_pre[2][1024][Lv][Bv];     // [dir][gate_row][t][b]
__device__ float g_hbuf[2][2][Hv][Bv];       // [parity][dir][k][b]
__device__ float g_hall[Lv][2*Hv][Bv];       // [t][c][b]
__device__ float g_parti[Bv*Lv*36];
__device__ float g_partj[Bv*Lv*36];
__device__ unsigned int g_cnt[2];

__global__ void k_init() {
  int i = blockIdx.x*blockDim.x + threadIdx.x;
  if (i < 2) g_cnt[i] = 0u;
  float* hb = &g_hbuf[0][0][0][0];
  if (i < 2*2*Hv*Bv) hb[i] = 0.f;
}

// ============ 1) input GEMM: pre[row][token], token = t*64+b ============
__global__ void __launch_bounds__(256) k_pre(
    const float* __restrict__ emb, const float* __restrict__ Wf, const float* __restrict__ Wb,
    const float* __restrict__ bihf, const float* __restrict__ bhhf,
    const float* __restrict__ bihb, const float* __restrict__ bhhb,
    const int* __restrict__ ids)
{
  __shared__ __align__(16) float A_s[20][64];
  __shared__ __align__(16) float W_s[20][64];
  __shared__ int id_s[64];
  int tid = threadIdx.x;
  int tokTile = blockIdx.x;   // 0..127
  int rowTile = blockIdx.y;   // 0..31
  if (tid < 64) {
    int token = tokTile*64 + tid;
    int b = token & 63, t = token >> 6;
    id_s[tid] = ids[b*Lv + t];
  }
  __syncthreads();

  int tokq = tid & 15, rowq = tid >> 4;
  float acc[4][4];
  #pragma unroll
  for (int i=0;i<4;i++)
    #pragma unroll
    for (int j=0;j<4;j++) acc[i][j] = 0.f;
  int rbase = rowTile*64;

  for (int kc = 0; kc < 15; kc++) {
    int k0 = kc*20;
    __syncthreads();
    for (int e = tid; e < 320; e += 256) {
      int d4 = e % 5, tok = e / 5;
      float4 v = *(const float4*)(emb + (size_t)id_s[tok]*Dv + k0 + d4*4);
      A_s[d4*4+0][tok] = v.x; A_s[d4*4+1][tok] = v.y;
      A_s[d4*4+2][tok] = v.z; A_s[d4*4+3][tok] = v.w;
    }
    for (int e = tid; e < 320; e += 256) {
      int d4 = e % 5, r = e / 5;
      int grow = rbase + r;
      const float* wp = (grow < 1024) ? (Wf + (size_t)grow*Dv) : (Wb + (size_t)(grow-1024)*Dv);
      float4 v = *(const float4*)(wp + k0 + d4*4);
      W_s[d4*4+0][r] = v.x; W_s[d4*4+1][r] = v.y;
      W_s[d4*4+2][r] = v.z; W_s[d4*4+3][r] = v.w;
    }
    __syncthreads();
    #pragma unroll
    for (int k = 0; k < 20; k++) {
      float4 av = *(const float4*)&A_s[k][tokq*4];
      float4 wv = *(const float4*)&W_s[k][rowq*4];
      float aj[4] = {av.x, av.y, av.z, av.w};
      float wi[4] = {wv.x, wv.y, wv.z, wv.w};
      #pragma unroll
      for (int i=0;i<4;i++)
        #pragma unroll
        for (int j=0;j<4;j++) acc[i][j] = fmaf(wi[i], aj[j], acc[i][j]);
    }
  }
  float* preFlat = &g_pre[0][0][0][0];
  int token0 = tokTile*64 + tokq*4;
  #pragma unroll
  for (int i=0;i<4;i++) {
    int grow = rbase + rowq*4 + i;
    float bias = (grow < 1024) ? (bihf[grow] + bhhf[grow])
                               : (bihb[grow-1024] + bhhb[grow-1024]);
    float4 o;
    o.x = acc[i][0]+bias; o.y = acc[i][1]+bias;
    o.z = acc[i][2]+bias; o.w = acc[i][3]+bias;
    *(float4*)(preFlat + (size_t)grow*8192 + token0) = o;
  }
}

// ============ 2) persistent BiLSTM: 128 CTAs = dir*64 + s ============
__global__ void __launch_bounds__(256,1) k_lstm(const float* __restrict__ Whhf,
                                                const float* __restrict__ Whhb)
{
  extern __shared__ float sm[];
  float* W_s  = sm;                 // 16*256 = 4096
  float* h_s  = sm + 4096;          // 256*64 = 16384
  float* gt_s = sm + 4096 + 16384;  // 16*64  = 1024

  int tid = threadIdx.x, cta = blockIdx.x;
  int dir = cta >> 6, s = cta & 63, k0 = s*4;
  const float* Whh = dir ? Whhb : Whhf;

  for (int e = tid; e < 4096; e += 256) {
    int r = e >> 8, k = e & 255;
    int grow = (r>>2)*256 + k0 + (r&3);
    W_s[e] = Whh[(size_t)grow*Hv + k];
  }
  __syncthreads();

  int w = tid >> 5, lane = tid & 31;
  int r0 = w*2, r1 = r0+1;
  int b0 = lane*2;
  int grow0 = (r0>>2)*256 + k0 + (r0&3);
  int grow1 = (r1>>2)*256 + k0 + (r1&3);
  const float* pre = &g_pre[dir][0][0][0];
  int j = tid >> 6, bb = tid & 63;
  float c = 0.f;

  for (int sidx = 0; sidx < Lv; sidx++) {
    int t = dir ? (Lv-1-sidx) : sidx;
    if (sidx > 0) {
      if (tid == 0) {
        unsigned tgt = (unsigned)(sidx*64);
        while (*((volatile unsigned int*)&g_cnt[dir]) < tgt) { }
      }
      __syncthreads();
      __threadfence();
    }
    // stage prev h (L2-coherent loads; L1 may be stale)
    {
      const float4* src = (const float4*)&g_hbuf[sidx&1][dir][0][0];
      float4* dst = (float4*)h_s;
      for (int e = tid; e < 4096; e += 256) dst[e] = __ldcg(&src[e]);
    }
    __syncthreads();

    float a00=0.f, a01=0.f, a10=0.f, a11=0.f;
    const float* w0 = &W_s[r0*256];
    const float* w1 = &W_s[r1*256];
    #pragma unroll 8
    for (int k = 0; k < 256; k++) {
      float2 h2 = *(const float2*)&h_s[k*64 + b0];
      float x0 = w0[k], x1 = w1[k];
      a00 = fmaf(x0, h2.x, a00); a01 = fmaf(x0, h2.y, a01);
      a10 = fmaf(x1, h2.x, a10); a11 = fmaf(x1, h2.y, a11);
    }
    float2 p0 = *(const float2*)&pre[(size_t)grow0*8192 + t*64 + b0];
    float2 p1 = *(const float2*)&pre[(size_t)grow1*8192 + t*64 + b0];
    gt_s[r0*64 + b0]   = a00 + p0.x;
    gt_s[r0*64 + b0+1] = a01 + p0.y;
    gt_s[r1*64 + b0]   = a10 + p1.x;
    gt_s[r1*64 + b0+1] = a11 + p1.y;
    __syncthreads();

    float iv = gt_s[(0*4+j)*64 + bb];
    float fv = gt_s[(1*4+j)*64 + bb];
    float gv = gt_s[(2*4+j)*64 + bb];
    float ov = gt_s[(3*4+j)*64 + bb];
    iv = 1.f/(1.f+__expf(-iv));
    fv = 1.f/(1.f+__expf(-fv));
    gv = tanhf(gv);
    ov = 1.f/(1.f+__expf(-ov));
    c = fv*c + iv*gv;
    float h = ov*tanhf(c);
    g_hbuf[(sidx+1)&1][dir][k0+j][bb] = h;
    g_hall[t][dir*Hv + k0 + j][bb] = h;
    __threadfence();
    __syncthreads();
    if (tid == 0) atomicAdd(&g_cnt[dir], 1u);
  }
}

// ============ 3) event scan: one CTA per batch ============
__global__ void __launch_bounds__(128) k_event(const float* __restrict__ Wev,
                                               const float* __restrict__ bev,
                                               float* __restrict__ out0)
{
  __shared__ float feat[548];
  __shared__ float logit_s[34];
  __shared__ float g_s[33];
  int b = blockIdx.x, tid = threadIdx.x, lane = tid & 31, w = tid >> 5;
  if (tid < 33) g_s[tid] = 0.f;
  __syncthreads();
  for (int t = 0; t < Lv; t++) {
    for (int cc = tid; cc < 512; cc += 128) feat[cc] = g_hall[t][cc][b];
    if (tid < 33) feat[512+tid] = g_s[tid];
    __syncthreads();
    for (int e = w; e < NEv; e += 4) {
      const float* wr = &Wev[(size_t)e*545];
      float acc = 0.f;
      for (int k = lane; k < 545; k += 32) acc = fmaf(wr[k], feat[k], acc);
      #pragma unroll
      for (int o = 16; o > 0; o >>= 1) acc += __shfl_xor_sync(0xffffffffu, acc, o);
      if (lane == 0) logit_s[e] = acc + bev[e];
    }
    __syncthreads();
    if (tid < NEv) out0[((size_t)b*Lv + t)*NEv + tid] = logit_s[tid];
    if (tid == 0) {
      int pm = 0; float mv = logit_s[0];
      for (int e = 1; e < NEv; e++) if (logit_s[e] > mv) { mv = logit_s[e]; pm = e; }
      if (pm > 0) g_s[pm-1] = 1.f;
    }
    __syncthreads();
  }
}

// ============ 4) part_i / part_j ============
__global__ void k_part(const float* __restrict__ Warg) {
  int t = blockIdx.x;
  int r = blockIdx.y*4 + threadIdx.y;  // 0..71
  int b = threadIdx.x;
  const float* wr = (r < 36) ? &Warg[(size_t)r*1024] : &Warg[(size_t)(r-36)*1024 + 512];
  const float* hp = &g_hall[t][0][0];
  float acc = 0.f;
  #pragma unroll 4
  for (int cc = 0; cc < 512; cc++) acc = fmaf(__ldg(&wr[cc]), hp[cc*64 + b], acc);
  if (r < 36) g_partj[((size_t)b*Lv + t)*36 + r]      = acc;
  else        g_parti[((size_t)b*Lv + t)*36 + (r-36)] = acc;
}

// ============ 5) broadcast add ============
__global__ void k_add(const float* __restrict__ barg, float* __restrict__ out1) {
  size_t o = (size_t)blockIdx.x*256 + threadIdx.x;
  if (o >= 37748736ull) return;
  int a = (int)(o % 36);
  size_t q = o / 36;
  int jj = (int)(q % 128); q /= 128;
  int ii = (int)(q % 128);
  int b  = (int)(q / 128);
  out1[o] = g_parti[((size_t)b*Lv + ii)*36 + a]
          + g_partj[((size_t)b*Lv + jj)*36 + a] + barg[a];
}

extern "C" void kernel_launch(void* const* d_in, const int* in_sizes, int n_in,
                              void* d_out, int out_size) {
  const float* emb  = (const float*)d_in[0];
  const float* Wihf = (const float*)d_in[1];
  const float* Whhf = (const float*)d_in[2];
  const float* bihf = (const float*)d_in[3];
  const float* bhhf = (const float*)d_in[4];
  const float* Wihb = (const float*)d_in[5];
  const float* Whhb = (const float*)d_in[6];
  const float* bihb = (const float*)d_in[7];
  const float* bhhb = (const float*)d_in[8];
  const float* Wev  = (const float*)d_in[9];
  const float* bev  = (const float*)d_in[10];
  const float* Warg = (const float*)d_in[11];
  const float* barg = (const float*)d_in[12];
  const int*   ids  = (const int*)d_in[13];
  float* out = (float*)d_out;

  cudaFuncSetAttribute(k_lstm, cudaFuncAttributeMaxDynamicSharedMemorySize, 86016);

  k_init<<<256, 256>>>();
  dim3 gp(128, 32);
  k_pre<<<gp, 256>>>(emb, Wihf, Wihb, bihf, bhhf, bihb, bhhb, ids);
  k_lstm<<<128, 256, 86016>>>(Whhf, Whhb);
  k_event<<<64, 128>>>(Wev, bev, out);
  dim3 bp(64, 4), gpp(128, 18);
  k_part<<<gpp, bp>>>(Warg);
  k_add<<<147456, 256>>>(barg, out + 278528);
}

// round 5
// speedup vs baseline: 1.2603x; 1.2603x over previous
#include <cuda_runtime.h>
#include <cuda_bf16.h>
#include <math.h>

#define Bv 64
#define Lv 128
#define Hv 256
#define NEv 34
#define Dv 300

// ---------------- device scratch ----------------
__device__ float g_pre[2][1024][Lv][Bv];     // [dir][gate_row][t][b]
__device__ float g_hbuf[2][2][Hv][Bv];       // [parity][dir][k][b]
__device__ float g_hall[Lv][2*Hv][Bv];       // [t][c][b]
__device__ float g_parti[Bv*Lv*36];
__device__ float g_partj[Bv*Lv*36];
__device__ unsigned int g_cnt[2];

__global__ void k_init() {
  int i = blockIdx.x*blockDim.x + threadIdx.x;
  if (i < 2) g_cnt[i] = 0u;
  float* hb = &g_hbuf[0][0][0][0];
  if (i < 2*2*Hv*Bv) hb[i] = 0.f;
}

// ============ 1) input GEMM: pre[row][token], token = t*64+b ============
__global__ void __launch_bounds__(256) k_pre(
    const float* __restrict__ emb, const float* __restrict__ Wf, const float* __restrict__ Wb,
    const float* __restrict__ bihf, const float* __restrict__ bhhf,
    const float* __restrict__ bihb, const float* __restrict__ bhhb,
    const int* __restrict__ ids)
{
  __shared__ __align__(16) float A_s[20][64];
  __shared__ __align__(16) float W_s[20][64];
  __shared__ int id_s[64];
  int tid = threadIdx.x;
  int tokTile = blockIdx.x;   // 0..127
  int rowTile = blockIdx.y;   // 0..31
  if (tid < 64) {
    int token = tokTile*64 + tid;
    int b = token & 63, t = token >> 6;
    id_s[tid] = ids[b*Lv + t];
  }
  __syncthreads();

  int tokq = tid & 15, rowq = tid >> 4;
  float acc[4][4];
  #pragma unroll
  for (int i=0;i<4;i++)
    #pragma unroll
    for (int j=0;j<4;j++) acc[i][j] = 0.f;
  int rbase = rowTile*64;

  for (int kc = 0; kc < 15; kc++) {
    int k0 = kc*20;
    __syncthreads();
    for (int e = tid; e < 320; e += 256) {
      int d4 = e % 5, tok = e / 5;
      float4 v = *(const float4*)(emb + (size_t)id_s[tok]*Dv + k0 + d4*4);
      A_s[d4*4+0][tok] = v.x; A_s[d4*4+1][tok] = v.y;
      A_s[d4*4+2][tok] = v.z; A_s[d4*4+3][tok] = v.w;
    }
    for (int e = tid; e < 320; e += 256) {
      int d4 = e % 5, r = e / 5;
      int grow = rbase + r;
      const float* wp = (grow < 1024) ? (Wf + (size_t)grow*Dv) : (Wb + (size_t)(grow-1024)*Dv);
      float4 v = *(const float4*)(wp + k0 + d4*4);
      W_s[d4*4+0][r] = v.x; W_s[d4*4+1][r] = v.y;
      W_s[d4*4+2][r] = v.z; W_s[d4*4+3][r] = v.w;
    }
    __syncthreads();
    #pragma unroll
    for (int k = 0; k < 20; k++) {
      float4 av = *(const float4*)&A_s[k][tokq*4];
      float4 wv = *(const float4*)&W_s[k][rowq*4];
      float aj[4] = {av.x, av.y, av.z, av.w};
      float wi[4] = {wv.x, wv.y, wv.z, wv.w};
      #pragma unroll
      for (int i=0;i<4;i++)
        #pragma unroll
        for (int j=0;j<4;j++) acc[i][j] = fmaf(wi[i], aj[j], acc[i][j]);
    }
  }
  float* preFlat = &g_pre[0][0][0][0];
  int token0 = tokTile*64 + tokq*4;
  #pragma unroll
  for (int i=0;i<4;i++) {
    int grow = rbase + rowq*4 + i;
    float bias = (grow < 1024) ? (bihf[grow] + bhhf[grow])
                               : (bihb[grow-1024] + bhhb[grow-1024]);
    float4 o;
    o.x = acc[i][0]+bias; o.y = acc[i][1]+bias;
    o.z = acc[i][2]+bias; o.w = acc[i][3]+bias;
    *(float4*)(preFlat + (size_t)grow*8192 + token0) = o;
  }
}

// ============ 2) persistent BiLSTM: 128 CTAs = dir*64 + s ============
__global__ void __launch_bounds__(256,1) k_lstm(const float* __restrict__ Whhf,
                                                const float* __restrict__ Whhb)
{
  extern __shared__ float sm[];
  float* W_s  = sm;                 // 16*256 = 4096
  float* h_s  = sm + 4096;          // 256*64 = 16384
  float* gt_s = sm + 4096 + 16384;  // 16*64  = 1024

  int tid = threadIdx.x, cta = blockIdx.x;
  int dir = cta >> 6, s = cta & 63, k0 = s*4;
  const float* Whh = dir ? Whhb : Whhf;

  for (int e = tid; e < 4096; e += 256) {
    int r = e >> 8, k = e & 255;
    int grow = (r>>2)*256 + k0 + (r&3);
    W_s[e] = Whh[(size_t)grow*Hv + k];
  }
  __syncthreads();

  int w = tid >> 5, lane = tid & 31;
  int r0 = w*2, r1 = r0+1;
  int b0 = lane*2;
  int grow0 = (r0>>2)*256 + k0 + (r0&3);
  int grow1 = (r1>>2)*256 + k0 + (r1&3);
  const float* pre = &g_pre[dir][0][0][0];
  int j = tid >> 6, bb = tid & 63;
  float c = 0.f;

  for (int sidx = 0; sidx < Lv; sidx++) {
    int t = dir ? (Lv-1-sidx) : sidx;
    if (sidx > 0) {
      if (tid == 0) {
        unsigned tgt = (unsigned)(sidx*64);
        while (*((volatile unsigned int*)&g_cnt[dir]) < tgt) { }
      }
      __syncthreads();
      __threadfence();
    }
    {
      const float4* src = (const float4*)&g_hbuf[sidx&1][dir][0][0];
      float4* dst = (float4*)h_s;
      for (int e = tid; e < 4096; e += 256) dst[e] = __ldcg(&src[e]);
    }
    __syncthreads();

    float a00=0.f, a01=0.f, a10=0.f, a11=0.f;
    const float* w0 = &W_s[r0*256];
    const float* w1 = &W_s[r1*256];
    #pragma unroll 8
    for (int k = 0; k < 256; k++) {
      float2 h2 = *(const float2*)&h_s[k*64 + b0];
      float x0 = w0[k], x1 = w1[k];
      a00 = fmaf(x0, h2.x, a00); a01 = fmaf(x0, h2.y, a01);
      a10 = fmaf(x1, h2.x, a10); a11 = fmaf(x1, h2.y, a11);
    }
    float2 p0 = *(const float2*)&pre[(size_t)grow0*8192 + t*64 + b0];
    float2 p1 = *(const float2*)&pre[(size_t)grow1*8192 + t*64 + b0];
    gt_s[r0*64 + b0]   = a00 + p0.x;
    gt_s[r0*64 + b0+1] = a01 + p0.y;
    gt_s[r1*64 + b0]   = a10 + p1.x;
    gt_s[r1*64 + b0+1] = a11 + p1.y;
    __syncthreads();

    float iv = gt_s[(0*4+j)*64 + bb];
    float fv = gt_s[(1*4+j)*64 + bb];
    float gv = gt_s[(2*4+j)*64 + bb];
    float ov = gt_s[(3*4+j)*64 + bb];
    iv = 1.f/(1.f+__expf(-iv));
    fv = 1.f/(1.f+__expf(-fv));
    gv = tanhf(gv);
    ov = 1.f/(1.f+__expf(-ov));
    c = fv*c + iv*gv;
    float h = ov*tanhf(c);
    g_hbuf[(sidx+1)&1][dir][k0+j][bb] = h;
    g_hall[t][dir*Hv + k0 + j][bb] = h;
    __threadfence();
    __syncthreads();
    if (tid == 0) atomicAdd(&g_cnt[dir], 1u);
  }
}

// ============ 3a) event base logits: out0[b][t][e] = h_t·Wev[e,:512] + bev[e] ============
__global__ void __launch_bounds__(256) k_evbase(const float* __restrict__ Wev,
                                                const float* __restrict__ bev,
                                                float* __restrict__ out0)
{
  __shared__ __align__(16) float W_s[34*64];   // [e][k] chunk
  __shared__ __align__(16) float h_s[64*68];   // [b][k] padded
  int t = blockIdx.x;
  int tid = threadIdx.x;
  int b = tid & 63;
  int g = tid >> 6;   // 0..3; this thread handles e = g, g+4, g+8, ...
  float acc[9];
  #pragma unroll
  for (int i=0;i<9;i++) acc[i] = 0.f;

  for (int c0 = 0; c0 < 512; c0 += 64) {
    __syncthreads();
    for (int e = tid; e < 34*64; e += 256) {
      int ee = e >> 6, kk = e & 63;
      W_s[e] = Wev[(size_t)ee*545 + c0 + kk];
    }
    for (int e = tid; e < 4096; e += 256) {
      int kk = e >> 6, bb = e & 63;
      h_s[bb*68 + kk] = g_hall[t][c0+kk][bb];
    }
    __syncthreads();
    #pragma unroll 4
    for (int k = 0; k < 64; k += 4) {
      float4 hv = *(const float4*)&h_s[b*68 + k];
      #pragma unroll
      for (int ii = 0; ii < 9; ii++) {
        int e = g + ii*4;
        if (e < 34) {
          float4 wv = *(const float4*)&W_s[e*64 + k];
          acc[ii] = fmaf(wv.x, hv.x, acc[ii]);
          acc[ii] = fmaf(wv.y, hv.y, acc[ii]);
          acc[ii] = fmaf(wv.z, hv.z, acc[ii]);
          acc[ii] = fmaf(wv.w, hv.w, acc[ii]);
        }
      }
    }
  }
  #pragma unroll
  for (int ii = 0; ii < 9; ii++) {
    int e = g + ii*4;
    if (e < 34)
      out0[((size_t)b*Lv + t)*NEv + e] = acc[ii] + bev[e];
  }
}

// ============ 3b) event scan: one warp per batch, tiny recurrence ============
__global__ void __launch_bounds__(32) k_evscan(const float* __restrict__ Wev,
                                               float* __restrict__ out0)
{
  int b = blockIdx.x;
  int lane = threadIdx.x;
  float add0 = 0.f, add1 = 0.f;     // accumulators for e=lane, e=lane+32
  unsigned long long gmask = 0ull;
  float* basep = out0 + (size_t)b*Lv*NEv;

  float l0 = basep[lane];
  float l1 = (lane < 2) ? basep[32 + lane] : 0.f;

  for (int t = 0; t < Lv; t++) {
    float n0 = 0.f, n1 = 0.f;
    if (t < Lv-1) {
      n0 = basep[(t+1)*NEv + lane];
      n1 = (lane < 2) ? basep[(t+1)*NEv + 32 + lane] : 0.f;
    }
    float v0 = l0 + add0;
    float v1 = (lane < 2) ? (l1 + add1) : -INFINITY;
    basep[t*NEv + lane] = v0;
    if (lane < 2) basep[t*NEv + 32 + lane] = v1;

    // argmax, lowest index wins ties (match jnp.argmax)
    float mv = v0; int mi = lane;
    if (lane < 2 && v1 > mv) { mv = v1; mi = lane + 32; }
    #pragma unroll
    for (int o = 16; o > 0; o >>= 1) {
      float ov = __shfl_xor_sync(0xffffffffu, mv, o);
      int   oi = __shfl_xor_sync(0xffffffffu, mi, o);
      if (ov > mv || (ov == mv && oi < mi)) { mv = ov; mi = oi; }
    }
    if (mi > 0) {
      unsigned long long bit = 1ull << (mi - 1);
      if (!(gmask & bit)) {
        gmask |= bit;
        add0 += Wev[(size_t)lane*545 + 512 + (mi-1)];
        if (lane < 2) add1 += Wev[(size_t)(lane+32)*545 + 512 + (mi-1)];
      }
    }
    l0 = n0; l1 = n1;
  }
}

// ============ 4) part_i / part_j ============
__global__ void k_part(const float* __restrict__ Warg) {
  int t = blockIdx.x;
  int r = blockIdx.y*4 + threadIdx.y;  // 0..71
  int b = threadIdx.x;
  const float* wr = (r < 36) ? &Warg[(size_t)r*1024] : &Warg[(size_t)(r-36)*1024 + 512];
  const float* hp = &g_hall[t][0][0];
  float acc = 0.f;
  #pragma unroll 4
  for (int cc = 0; cc < 512; cc++) acc = fmaf(__ldg(&wr[cc]), hp[cc*64 + b], acc);
  if (r < 36) g_partj[((size_t)b*Lv + t)*36 + r]      = acc;
  else        g_parti[((size_t)b*Lv + t)*36 + (r-36)] = acc;
}

// ============ 5) broadcast add ============
__global__ void k_add(const float* __restrict__ barg, float* __restrict__ out1) {
  size_t o = (size_t)blockIdx.x*256 + threadIdx.x;
  if (o >= 37748736ull) return;
  int a = (int)(o % 36);
  size_t q = o / 36;
  int jj = (int)(q % 128); q /= 128;
  int ii = (int)(q % 128);
  int b  = (int)(q / 128);
  out1[o] = g_parti[((size_t)b*Lv + ii)*36 + a]
          + g_partj[((size_t)b*Lv + jj)*36 + a] + barg[a];
}

extern "C" void kernel_launch(void* const* d_in, const int* in_sizes, int n_in,
                              void* d_out, int out_size) {
  const float* emb  = (const float*)d_in[0];
  const float* Wihf = (const float*)d_in[1];
  const float* Whhf = (const float*)d_in[2];
  const float* bihf = (const float*)d_in[3];
  const float* bhhf = (const float*)d_in[4];
  const float* Wihb = (const float*)d_in[5];
  const float* Whhb = (const float*)d_in[6];
  const float* bihb = (const float*)d_in[7];
  const float* bhhb = (const float*)d_in[8];
  const float* Wev  = (const float*)d_in[9];
  const float* bev  = (const float*)d_in[10];
  const float* Warg = (const float*)d_in[11];
  const float* barg = (const float*)d_in[12];
  const int*   ids  = (const int*)d_in[13];
  float* out = (float*)d_out;

  cudaFuncSetAttribute(k_lstm, cudaFuncAttributeMaxDynamicSharedMemorySize, 86016);

  k_init<<<256, 256>>>();
  dim3 gp(128, 32);
  k_pre<<<gp, 256>>>(emb, Wihf, Wihb, bihf, bhhf, bihb, bhhb, ids);
  k_lstm<<<128, 256, 86016>>>(Whhf, Whhb);
  k_evbase<<<128, 256>>>(Wev, bev, out);
  k_evscan<<<64, 32>>>(Wev, out);
  dim3 bp(64, 4), gpp(128, 18);
  k_part<<<gpp, bp>>>(Warg);
  k_add<<<147456, 256>>>(barg, out + 278528);
}